// round 13
// baseline (speedup 1.0000x reference)
#include <cuda_runtime.h>
#include <math.h>

#define NN 20000
#define EE 150000

// ---------------- scratch (static __device__ arrays; no allocation) -------
__device__ float g_xl1[NN * 512];
__device__ float g_xr1[NN * 512];
__device__ float g_h1 [NN * 512];
__device__ float g_xl2[NN * 128];
__device__ float g_xr2[NN * 128];
__device__ float g_loopea[NN * 2];
__device__ float g_sea  [NN * 2];
__device__ int   g_degI  [NN];
__device__ int   g_cursor[NN];
__device__ int   g_rowptr[NN + 1];
__device__ int   g_eid   [EE];

// ---------------- helpers ------------------------------------------------
__device__ __forceinline__ float elu1(float x) {
    return x > 0.f ? x : (expf(x) - 1.f);
}
__device__ __forceinline__ float lrelu(float x) {
    return x > 0.f ? x : 0.2f * x;
}
__device__ __forceinline__ float warpsum_all(float v) {   // result in all lanes
    #pragma unroll
    for (int o = 16; o > 0; o >>= 1) v += __shfl_xor_sync(0xffffffffu, v, o);
    return v;
}
__device__ __forceinline__ float warpsum(float v) {
    #pragma unroll
    for (int o = 16; o > 0; o >>= 1) v += __shfl_down_sync(0xffffffffu, v, o);
    return v;
}
// packed fp32x2 FMA (FFMA2) — only reachable via PTX fma.rn.f32x2
__device__ __forceinline__ void ffma2(unsigned long long& acc,
                                      unsigned long long a, unsigned long long b) {
    asm("fma.rn.f32x2 %0, %1, %2, %3;" : "=l"(acc) : "l"(a), "l"(b), "l"(acc));
}
__device__ __forceinline__ unsigned long long splat2(float w) {
    unsigned long long r;
    asm("mov.b64 %0, {%1, %1};" : "=l"(r) : "f"(w));
    return r;
}
__device__ __forceinline__ void unpack2(float& lo, float& hi, unsigned long long v) {
    asm("mov.b64 {%0, %1}, %2;" : "=f"(lo), "=f"(hi) : "l"(v));
}

// ---------------- init: zero counters ------------------------------------
__global__ void k_init() {
    int n = blockIdx.x * blockDim.x + threadIdx.x;
    if (n >= NN) return;
    g_degI[n] = 0;
    g_cursor[n] = 0;
    g_sea[2 * n] = 0.f; g_sea[2 * n + 1] = 0.f;
}

// ---------------- per-edge: degree count + edge-attr sum ------------------
__global__ void k_pre(const int* __restrict__ dst, const float* __restrict__ ea) {
    int e = blockIdx.x * blockDim.x + threadIdx.x;
    if (e >= EE) return;
    int d = dst[e];
    atomicAdd(&g_degI[d], 1);
    atomicAdd(&g_sea[2 * d],     ea[2 * e]);
    atomicAdd(&g_sea[2 * d + 1], ea[2 * e + 1]);
}

// ---------------- exclusive prefix sum over degrees (single block) --------
// warp-shuffle scan: 3 syncs per 1024-tile instead of ~20
__global__ void k_scan() {
    __shared__ int warp_sums[32];
    __shared__ int s_carry;
    int tid = threadIdx.x;
    int wid = tid >> 5, lane = tid & 31;
    if (tid == 0) { s_carry = 0; g_rowptr[0] = 0; }
    __syncthreads();
    for (int base = 0; base < NN; base += 1024) {
        int v = (base + tid < NN) ? g_degI[base + tid] : 0;
        int x = v;                                    // inclusive warp scan
        #pragma unroll
        for (int o = 1; o < 32; o <<= 1) {
            int t = __shfl_up_sync(0xffffffffu, x, o);
            if (lane >= o) x += t;
        }
        if (lane == 31) warp_sums[wid] = x;
        __syncthreads();
        if (wid == 0) {
            int s = warp_sums[lane];
            #pragma unroll
            for (int o = 1; o < 32; o <<= 1) {
                int t = __shfl_up_sync(0xffffffffu, s, o);
                if (lane >= o) s += t;
            }
            warp_sums[lane] = s;
        }
        __syncthreads();
        int add = ((wid > 0) ? warp_sums[wid - 1] : 0) + s_carry;
        if (base + tid < NN) g_rowptr[base + tid + 1] = x + add;
        __syncthreads();
        if (tid == 0) s_carry += warp_sums[31];
        __syncthreads();
    }
}

// ---------------- CSR placement ------------------------------------------
__global__ void k_place(const int* __restrict__ dst) {
    int e = blockIdx.x * blockDim.x + threadIdx.x;
    if (e >= EE) return;
    int d = dst[e];
    int pos = g_rowptr[d] + atomicAdd(&g_cursor[d], 1);
    g_eid[pos] = e;
}

// ---------------- self-loop edge-attr mean --------------------------------
__global__ void k_loopea_norm() {
    int n = blockIdx.x * blockDim.x + threadIdx.x;
    if (n >= NN) return;
    float d = fmaxf((float)g_degI[n], 1.f);
    g_loopea[2 * n]     = g_sea[2 * n]     / d;
    g_loopea[2 * n + 1] = g_sea[2 * n + 1] / d;
}

// ---------------- layer1 projections: embed + dual GEMM K=37, FFMA2 ------
// 512 threads (thread j = output col), 16 nodes/block (reg-safe at 512thr),
// node-pair accumulators; smem transposed sh[k*18+n] for broadcast LDS.64.
__global__ void __launch_bounds__(512) k_gemm1(
        const float* __restrict__ x, const int* __restrict__ rtype,
        const float* __restrict__ aaemb,
        const float* __restrict__ Wl, const float* __restrict__ Wr) {
    __shared__ __align__(16) float sh[37 * 18];
    int n0 = blockIdx.x * 16;
    int j = threadIdx.x;
    for (int t = j; t < 16 * 37; t += 512) {
        int n = t / 37, k = t - n * 37;
        int node = n0 + n;
        float v = 0.f;
        if (node < NN) v = (k < 5) ? x[node * 5 + k] : aaemb[rtype[node] * 32 + (k - 5)];
        sh[k * 18 + n] = v;
    }
    __syncthreads();
    unsigned long long accl[8], accr[8];
    #pragma unroll
    for (int p = 0; p < 8; p++) { accl[p] = 0ull; accr[p] = 0ull; }
    for (int k = 0; k < 37; k++) {
        unsigned long long wl2 = splat2(Wl[k * 512 + j]);
        unsigned long long wr2 = splat2(Wr[k * 512 + j]);
        const unsigned long long* row = (const unsigned long long*)&sh[k * 18];
        #pragma unroll
        for (int p = 0; p < 8; p++) {
            unsigned long long h2 = row[p];
            ffma2(accl[p], h2, wl2);
            ffma2(accr[p], h2, wr2);
        }
    }
    #pragma unroll
    for (int p = 0; p < 8; p++) {
        float l0, l1, r0, r1;
        unpack2(l0, l1, accl[p]);
        unpack2(r0, r1, accr[p]);
        int na = n0 + 2 * p, nb = na + 1;
        if (na < NN) { g_xl1[(long)na * 512 + j] = l0; g_xr1[(long)na * 512 + j] = r0; }
        if (nb < NN) { g_xl1[(long)nb * 512 + j] = l1; g_xr1[(long)nb * 512 + j] = r1; }
    }
}

// ---------------- layer1 fused attention+softmax+aggregate ----------------
// block = 128 threads = 4 warps; warp h = head h of node blockIdx.x.
// Edge metadata preloaded per 32-chunk; edge loop unrolled x2 for ILP
// across the two shuffle-reduction chains.
__global__ void k_node1(const int* __restrict__ src, const float* __restrict__ ea,
                        const float* __restrict__ We, const float* __restrict__ att,
                        const float* __restrict__ b1) {
    int n = blockIdx.x;
    int warp = threadIdx.x >> 5, lane = threadIdx.x & 31;
    int col = warp * 128 + lane * 4;
    float we0[4], we1[4], at[4];
    #pragma unroll
    for (int i = 0; i < 4; i++) {
        we0[i] = We[col + i];
        we1[i] = We[512 + col + i];
        at[i]  = att[col + i];
    }
    float4 vr = *(const float4*)&g_xr1[(long)n * 512 + col];
    float den = 0.f;
    float ax = 0.f, ay = 0.f, az = 0.f, aw = 0.f;
    int beg = g_rowptr[n], end = g_rowptr[n + 1];
    for (int chunk = beg; chunk < end; chunk += 32) {
        int cnt = min(32, end - chunk);
        int   myS  = 0;
        float myA0 = 0.f, myA1 = 0.f;
        if (lane < cnt) {
            int e = g_eid[chunk + lane];
            myS  = src[e];
            myA0 = ea[2 * e];
            myA1 = ea[2 * e + 1];
        }
        int t = 0;
        for (; t + 2 <= cnt; t += 2) {
            int   s0  = __shfl_sync(0xffffffffu, myS,  t);
            int   s1  = __shfl_sync(0xffffffffu, myS,  t + 1);
            float e00 = __shfl_sync(0xffffffffu, myA0, t);
            float e01 = __shfl_sync(0xffffffffu, myA1, t);
            float e10 = __shfl_sync(0xffffffffu, myA0, t + 1);
            float e11 = __shfl_sync(0xffffffffu, myA1, t + 1);
            float4 vl0 = *(const float4*)&g_xl1[(long)s0 * 512 + col];
            float4 vl1 = *(const float4*)&g_xl1[(long)s1 * 512 + col];
            float p0 = lrelu(vl0.x + vr.x + fmaf(e00, we0[0], e01 * we1[0])) * at[0]
                     + lrelu(vl0.y + vr.y + fmaf(e00, we0[1], e01 * we1[1])) * at[1]
                     + lrelu(vl0.z + vr.z + fmaf(e00, we0[2], e01 * we1[2])) * at[2]
                     + lrelu(vl0.w + vr.w + fmaf(e00, we0[3], e01 * we1[3])) * at[3];
            float p1 = lrelu(vl1.x + vr.x + fmaf(e10, we0[0], e11 * we1[0])) * at[0]
                     + lrelu(vl1.y + vr.y + fmaf(e10, we0[1], e11 * we1[1])) * at[1]
                     + lrelu(vl1.z + vr.z + fmaf(e10, we0[2], e11 * we1[2])) * at[2]
                     + lrelu(vl1.w + vr.w + fmaf(e10, we0[3], e11 * we1[3])) * at[3];
            float w0 = warpsum_all(p0);
            float w1 = warpsum_all(p1);
            float pe0 = __expf(w0);
            float pe1 = __expf(w1);
            den += pe0 + pe1;
            ax = fmaf(pe0, vl0.x, fmaf(pe1, vl1.x, ax));
            ay = fmaf(pe0, vl0.y, fmaf(pe1, vl1.y, ay));
            az = fmaf(pe0, vl0.z, fmaf(pe1, vl1.z, az));
            aw = fmaf(pe0, vl0.w, fmaf(pe1, vl1.w, aw));
        }
        if (t < cnt) {
            int   s0  = __shfl_sync(0xffffffffu, myS,  t);
            float e00 = __shfl_sync(0xffffffffu, myA0, t);
            float e01 = __shfl_sync(0xffffffffu, myA1, t);
            float4 vl0 = *(const float4*)&g_xl1[(long)s0 * 512 + col];
            float p0 = lrelu(vl0.x + vr.x + fmaf(e00, we0[0], e01 * we1[0])) * at[0]
                     + lrelu(vl0.y + vr.y + fmaf(e00, we0[1], e01 * we1[1])) * at[1]
                     + lrelu(vl0.z + vr.z + fmaf(e00, we0[2], e01 * we1[2])) * at[2]
                     + lrelu(vl0.w + vr.w + fmaf(e00, we0[3], e01 * we1[3])) * at[3];
            float pe0 = __expf(warpsum_all(p0));
            den += pe0;
            ax = fmaf(pe0, vl0.x, ax);
            ay = fmaf(pe0, vl0.y, ay);
            az = fmaf(pe0, vl0.z, az);
            aw = fmaf(pe0, vl0.w, aw);
        }
    }
    {   // self loop
        float ea0 = g_loopea[2 * n], ea1 = g_loopea[2 * n + 1];
        float4 vl = *(const float4*)&g_xl1[(long)n * 512 + col];
        float p = lrelu(vl.x + vr.x + fmaf(ea0, we0[0], ea1 * we1[0])) * at[0]
                + lrelu(vl.y + vr.y + fmaf(ea0, we0[1], ea1 * we1[1])) * at[1]
                + lrelu(vl.z + vr.z + fmaf(ea0, we0[2], ea1 * we1[2])) * at[2]
                + lrelu(vl.w + vr.w + fmaf(ea0, we0[3], ea1 * we1[3])) * at[3];
        float pe = __expf(warpsum_all(p));
        den += pe;
        ax = fmaf(pe, vl.x, ax);
        ay = fmaf(pe, vl.y, ay);
        az = fmaf(pe, vl.z, az);
        aw = fmaf(pe, vl.w, aw);
    }
    float inv = 1.f / den;
    float4 o;
    o.x = elu1(fmaf(ax, inv, b1[col + 0]));
    o.y = elu1(fmaf(ay, inv, b1[col + 1]));
    o.z = elu1(fmaf(az, inv, b1[col + 2]));
    o.w = elu1(fmaf(aw, inv, b1[col + 3]));
    *(float4*)&g_h1[(long)n * 512 + col] = o;
}

// ---------------- layer2 projections: dual GEMM K=512, FFMA2 -------------
// 128 threads (thread j = output col), 32 nodes/block (dynamic smem 69.6KB).
__global__ void __launch_bounds__(128) k_gemm2(
        const float* __restrict__ Wl, const float* __restrict__ Wr) {
    extern __shared__ __align__(16) float sh[];   // [512 * 34]
    int n0 = blockIdx.x * 32;
    int j = threadIdx.x;
    for (int t = j; t < 32 * 512; t += 128) {
        int n = t >> 9, k = t & 511;
        int node = n0 + n;
        sh[k * 34 + n] = (node < NN) ? g_h1[(long)node * 512 + k] : 0.f;
    }
    __syncthreads();
    unsigned long long accl[16], accr[16];
    #pragma unroll
    for (int p = 0; p < 16; p++) { accl[p] = 0ull; accr[p] = 0ull; }
    for (int k = 0; k < 512; k++) {
        unsigned long long wl2 = splat2(Wl[k * 128 + j]);
        unsigned long long wr2 = splat2(Wr[k * 128 + j]);
        const unsigned long long* row = (const unsigned long long*)&sh[k * 34];
        #pragma unroll
        for (int p = 0; p < 16; p++) {
            unsigned long long h2 = row[p];
            ffma2(accl[p], h2, wl2);
            ffma2(accr[p], h2, wr2);
        }
    }
    #pragma unroll
    for (int p = 0; p < 16; p++) {
        float l0, l1, r0, r1;
        unpack2(l0, l1, accl[p]);
        unpack2(r0, r1, accr[p]);
        int na = n0 + 2 * p, nb = na + 1;
        if (na < NN) { g_xl2[(long)na * 128 + j] = l0; g_xr2[(long)na * 128 + j] = r0; }
        if (nb < NN) { g_xl2[(long)nb * 128 + j] = l1; g_xr2[(long)nb * 128 + j] = r1; }
    }
}

// ---------------- layer2 fused attention+softmax+aggregate+FC -------------
// warp per node (1 head, 128 cols, 4 cols/lane); edge loop unrolled x2.
__global__ void k_node2(const int* __restrict__ src, const float* __restrict__ ea,
                        const float* __restrict__ We, const float* __restrict__ att,
                        const float* __restrict__ b2, const float* __restrict__ Wfc,
                        const float* __restrict__ bfc, float* __restrict__ out) {
    int warp = threadIdx.x >> 5, lane = threadIdx.x & 31;
    int n = blockIdx.x * 8 + warp;
    if (n >= NN) return;
    int col = lane * 4;
    float we0[4], we1[4], at[4];
    #pragma unroll
    for (int i = 0; i < 4; i++) {
        we0[i] = We[col + i];
        we1[i] = We[128 + col + i];
        at[i]  = att[col + i];
    }
    float4 vr = *(const float4*)&g_xr2[(long)n * 128 + col];
    float den = 0.f;
    float ax = 0.f, ay = 0.f, az = 0.f, aw = 0.f;
    int beg = g_rowptr[n], end = g_rowptr[n + 1];
    for (int chunk = beg; chunk < end; chunk += 32) {
        int cnt = min(32, end - chunk);
        int   myS  = 0;
        float myA0 = 0.f, myA1 = 0.f;
        if (lane < cnt) {
            int e = g_eid[chunk + lane];
            myS  = src[e];
            myA0 = ea[2 * e];
            myA1 = ea[2 * e + 1];
        }
        int t = 0;
        for (; t + 2 <= cnt; t += 2) {
            int   s0  = __shfl_sync(0xffffffffu, myS,  t);
            int   s1  = __shfl_sync(0xffffffffu, myS,  t + 1);
            float e00 = __shfl_sync(0xffffffffu, myA0, t);
            float e01 = __shfl_sync(0xffffffffu, myA1, t);
            float e10 = __shfl_sync(0xffffffffu, myA0, t + 1);
            float e11 = __shfl_sync(0xffffffffu, myA1, t + 1);
            float4 vl0 = *(const float4*)&g_xl2[(long)s0 * 128 + col];
            float4 vl1 = *(const float4*)&g_xl2[(long)s1 * 128 + col];
            float p0 = lrelu(vl0.x + vr.x + fmaf(e00, we0[0], e01 * we1[0])) * at[0]
                     + lrelu(vl0.y + vr.y + fmaf(e00, we0[1], e01 * we1[1])) * at[1]
                     + lrelu(vl0.z + vr.z + fmaf(e00, we0[2], e01 * we1[2])) * at[2]
                     + lrelu(vl0.w + vr.w + fmaf(e00, we0[3], e01 * we1[3])) * at[3];
            float p1 = lrelu(vl1.x + vr.x + fmaf(e10, we0[0], e11 * we1[0])) * at[0]
                     + lrelu(vl1.y + vr.y + fmaf(e10, we0[1], e11 * we1[1])) * at[1]
                     + lrelu(vl1.z + vr.z + fmaf(e10, we0[2], e11 * we1[2])) * at[2]
                     + lrelu(vl1.w + vr.w + fmaf(e10, we0[3], e11 * we1[3])) * at[3];
            float w0 = warpsum_all(p0);
            float w1 = warpsum_all(p1);
            float pe0 = __expf(w0);
            float pe1 = __expf(w1);
            den += pe0 + pe1;
            ax = fmaf(pe0, vl0.x, fmaf(pe1, vl1.x, ax));
            ay = fmaf(pe0, vl0.y, fmaf(pe1, vl1.y, ay));
            az = fmaf(pe0, vl0.z, fmaf(pe1, vl1.z, az));
            aw = fmaf(pe0, vl0.w, fmaf(pe1, vl1.w, aw));
        }
        if (t < cnt) {
            int   s0  = __shfl_sync(0xffffffffu, myS,  t);
            float e00 = __shfl_sync(0xffffffffu, myA0, t);
            float e01 = __shfl_sync(0xffffffffu, myA1, t);
            float4 vl0 = *(const float4*)&g_xl2[(long)s0 * 128 + col];
            float p0 = lrelu(vl0.x + vr.x + fmaf(e00, we0[0], e01 * we1[0])) * at[0]
                     + lrelu(vl0.y + vr.y + fmaf(e00, we0[1], e01 * we1[1])) * at[1]
                     + lrelu(vl0.z + vr.z + fmaf(e00, we0[2], e01 * we1[2])) * at[2]
                     + lrelu(vl0.w + vr.w + fmaf(e00, we0[3], e01 * we1[3])) * at[3];
            float pe0 = __expf(warpsum_all(p0));
            den += pe0;
            ax = fmaf(pe0, vl0.x, ax);
            ay = fmaf(pe0, vl0.y, ay);
            az = fmaf(pe0, vl0.z, az);
            aw = fmaf(pe0, vl0.w, aw);
        }
    }
    {   // self loop
        float ea0 = g_loopea[2 * n], ea1 = g_loopea[2 * n + 1];
        float4 vl = *(const float4*)&g_xl2[(long)n * 128 + col];
        float p = lrelu(vl.x + vr.x + fmaf(ea0, we0[0], ea1 * we1[0])) * at[0]
                + lrelu(vl.y + vr.y + fmaf(ea0, we0[1], ea1 * we1[1])) * at[1]
                + lrelu(vl.z + vr.z + fmaf(ea0, we0[2], ea1 * we1[2])) * at[2]
                + lrelu(vl.w + vr.w + fmaf(ea0, we0[3], ea1 * we1[3])) * at[3];
        float pe = __expf(warpsum_all(p));
        den += pe;
        ax = fmaf(pe, vl.x, ax);
        ay = fmaf(pe, vl.y, ay);
        az = fmaf(pe, vl.z, az);
        aw = fmaf(pe, vl.w, aw);
    }
    float inv = 1.f / den;
    float h0 = elu1(fmaf(ax, inv, b2[col + 0]));
    float h1 = elu1(fmaf(ay, inv, b2[col + 1]));
    float h2 = elu1(fmaf(az, inv, b2[col + 2]));
    float h3 = elu1(fmaf(aw, inv, b2[col + 3]));
    float a0 = h0 * Wfc[(col + 0) * 2] + h1 * Wfc[(col + 1) * 2]
             + h2 * Wfc[(col + 2) * 2] + h3 * Wfc[(col + 3) * 2];
    float a1 = h0 * Wfc[(col + 0) * 2 + 1] + h1 * Wfc[(col + 1) * 2 + 1]
             + h2 * Wfc[(col + 2) * 2 + 1] + h3 * Wfc[(col + 3) * 2 + 1];
    a0 = warpsum(a0);
    a1 = warpsum(a1);
    if (lane == 0) {
        out[n * 2]     = a0 + bfc[0];
        out[n * 2 + 1] = a1 + bfc[1];
    }
}

// ---------------- launcher ----------------------------------------------
extern "C" void kernel_launch(void* const* d_in, const int* in_sizes, int n_in,
                              void* d_out, int out_size) {
    const float* x     = (const float*)d_in[0];
    const int*   ei    = (const int*)  d_in[1];
    const float* ea    = (const float*)d_in[2];
    const int*   rtype = (const int*)  d_in[3];
    const float* aaemb = (const float*)d_in[4];
    const float* W1l   = (const float*)d_in[5];
    const float* W1r   = (const float*)d_in[6];
    const float* W1e   = (const float*)d_in[7];
    const float* att1  = (const float*)d_in[8];
    const float* b1    = (const float*)d_in[9];
    const float* W2l   = (const float*)d_in[10];
    const float* W2r   = (const float*)d_in[11];
    const float* W2e   = (const float*)d_in[12];
    const float* att2  = (const float*)d_in[13];
    const float* b2    = (const float*)d_in[14];
    const float* Wfc   = (const float*)d_in[15];
    const float* bfc   = (const float*)d_in[16];
    float* out = (float*)d_out;

    const int* src = ei;
    const int* dst = ei + EE;

    const int smem2 = 512 * 34 * sizeof(float);   // 69.6 KB dynamic
    cudaFuncSetAttribute(k_gemm2, cudaFuncAttributeMaxDynamicSharedMemorySize, smem2);

    k_init<<<(NN + 255) / 256, 256>>>();
    k_pre<<<(EE + 255) / 256, 256>>>(dst, ea);
    k_scan<<<1, 1024>>>();
    k_place<<<(EE + 255) / 256, 256>>>(dst);
    k_loopea_norm<<<(NN + 255) / 256, 256>>>();
    k_gemm1<<<(NN + 15) / 16, 512>>>(x, rtype, aaemb, W1l, W1r);
    k_node1<<<NN, 128>>>(src, ea, W1e, att1, b1);
    k_gemm2<<<(NN + 31) / 32, 128, smem2>>>(W2l, W2r);
    k_node2<<<(NN + 7) / 8, 256>>>(src, ea, W2e, att2, b2, Wfc, bfc, out);
}

// round 15
// speedup vs baseline: 1.3404x; 1.3404x over previous
#include <cuda_runtime.h>
#include <math.h>

#define NN 20000
#define EE 150000

// ---------------- scratch (static __device__ arrays; no allocation) -------
__device__ float g_xl1[NN * 512];
__device__ float g_xr1[NN * 512];
__device__ float g_h1 [NN * 512];
__device__ float g_xl2[NN * 128];
__device__ float g_xr2[NN * 128];
__device__ float g_loopea[NN * 2];
__device__ float g_sea  [NN * 2];
__device__ int   g_degI  [NN];
__device__ int   g_cursor[NN];
__device__ int   g_rowptr[NN + 1];
__device__ int   g_eid   [EE];

// ---------------- helpers ------------------------------------------------
__device__ __forceinline__ float elu1(float x) {
    return x > 0.f ? x : (expf(x) - 1.f);
}
__device__ __forceinline__ float lrelu(float x) {
    return x > 0.f ? x : 0.2f * x;
}
__device__ __forceinline__ float warpsum_all(float v) {   // result in all lanes
    #pragma unroll
    for (int o = 16; o > 0; o >>= 1) v += __shfl_xor_sync(0xffffffffu, v, o);
    return v;
}
__device__ __forceinline__ float warpsum(float v) {
    #pragma unroll
    for (int o = 16; o > 0; o >>= 1) v += __shfl_down_sync(0xffffffffu, v, o);
    return v;
}
// packed fp32x2 FMA (FFMA2) — only reachable via PTX fma.rn.f32x2
__device__ __forceinline__ void ffma2(unsigned long long& acc,
                                      unsigned long long a, unsigned long long b) {
    asm("fma.rn.f32x2 %0, %1, %2, %3;" : "=l"(acc) : "l"(a), "l"(b), "l"(acc));
}
__device__ __forceinline__ unsigned long long splat2(float w) {
    unsigned long long r;
    asm("mov.b64 %0, {%1, %1};" : "=l"(r) : "f"(w));
    return r;
}
__device__ __forceinline__ void unpack2(float& lo, float& hi, unsigned long long v) {
    asm("mov.b64 {%0, %1}, %2;" : "=f"(lo), "=f"(hi) : "l"(v));
}

// ---------------- init: zero counters ------------------------------------
__global__ void k_init() {
    int n = blockIdx.x * blockDim.x + threadIdx.x;
    if (n >= NN) return;
    g_degI[n] = 0;
    g_cursor[n] = 0;
    g_sea[2 * n] = 0.f; g_sea[2 * n + 1] = 0.f;
}

// ---------------- per-edge: degree count + edge-attr sum ------------------
__global__ void k_pre(const int* __restrict__ dst, const float* __restrict__ ea) {
    int e = blockIdx.x * blockDim.x + threadIdx.x;
    if (e >= EE) return;
    int d = dst[e];
    atomicAdd(&g_degI[d], 1);
    atomicAdd(&g_sea[2 * d],     ea[2 * e]);
    atomicAdd(&g_sea[2 * d + 1], ea[2 * e + 1]);
}

// ---------------- exclusive prefix sum over degrees (single block) --------
// warp-shuffle scan: 3 syncs per 1024-tile instead of ~20
__global__ void k_scan() {
    __shared__ int warp_sums[32];
    __shared__ int s_carry;
    int tid = threadIdx.x;
    int wid = tid >> 5, lane = tid & 31;
    if (tid == 0) { s_carry = 0; g_rowptr[0] = 0; }
    __syncthreads();
    for (int base = 0; base < NN; base += 1024) {
        int v = (base + tid < NN) ? g_degI[base + tid] : 0;
        int x = v;                                    // inclusive warp scan
        #pragma unroll
        for (int o = 1; o < 32; o <<= 1) {
            int t = __shfl_up_sync(0xffffffffu, x, o);
            if (lane >= o) x += t;
        }
        if (lane == 31) warp_sums[wid] = x;
        __syncthreads();
        if (wid == 0) {
            int s = warp_sums[lane];
            #pragma unroll
            for (int o = 1; o < 32; o <<= 1) {
                int t = __shfl_up_sync(0xffffffffu, s, o);
                if (lane >= o) s += t;
            }
            warp_sums[lane] = s;
        }
        __syncthreads();
        int add = ((wid > 0) ? warp_sums[wid - 1] : 0) + s_carry;
        if (base + tid < NN) g_rowptr[base + tid + 1] = x + add;
        __syncthreads();
        if (tid == 0) s_carry += warp_sums[31];
        __syncthreads();
    }
}

// ---------------- CSR placement ------------------------------------------
__global__ void k_place(const int* __restrict__ dst) {
    int e = blockIdx.x * blockDim.x + threadIdx.x;
    if (e >= EE) return;
    int d = dst[e];
    int pos = g_rowptr[d] + atomicAdd(&g_cursor[d], 1);
    g_eid[pos] = e;
}

// ---------------- self-loop edge-attr mean --------------------------------
__global__ void k_loopea_norm() {
    int n = blockIdx.x * blockDim.x + threadIdx.x;
    if (n >= NN) return;
    float d = fmaxf((float)g_degI[n], 1.f);
    g_loopea[2 * n]     = g_sea[2 * n]     / d;
    g_loopea[2 * n + 1] = g_sea[2 * n + 1] / d;
}

// ---------------- layer1 projections: embed + dual GEMM K=37, FFMA2 ------
// 512 threads (thread j = output col), 16 nodes/block, node-pair accumulators.
__global__ void __launch_bounds__(512) k_gemm1(
        const float* __restrict__ x, const int* __restrict__ rtype,
        const float* __restrict__ aaemb,
        const float* __restrict__ Wl, const float* __restrict__ Wr) {
    __shared__ __align__(16) float sh[37 * 18];
    int n0 = blockIdx.x * 16;
    int j = threadIdx.x;
    for (int t = j; t < 16 * 37; t += 512) {
        int n = t / 37, k = t - n * 37;
        int node = n0 + n;
        float v = 0.f;
        if (node < NN) v = (k < 5) ? x[node * 5 + k] : aaemb[rtype[node] * 32 + (k - 5)];
        sh[k * 18 + n] = v;
    }
    __syncthreads();
    unsigned long long accl[8], accr[8];
    #pragma unroll
    for (int p = 0; p < 8; p++) { accl[p] = 0ull; accr[p] = 0ull; }
    for (int k = 0; k < 37; k++) {
        unsigned long long wl2 = splat2(Wl[k * 512 + j]);
        unsigned long long wr2 = splat2(Wr[k * 512 + j]);
        const unsigned long long* row = (const unsigned long long*)&sh[k * 18];
        #pragma unroll
        for (int p = 0; p < 8; p++) {
            unsigned long long h2 = row[p];
            ffma2(accl[p], h2, wl2);
            ffma2(accr[p], h2, wr2);
        }
    }
    #pragma unroll
    for (int p = 0; p < 8; p++) {
        float l0, l1, r0, r1;
        unpack2(l0, l1, accl[p]);
        unpack2(r0, r1, accr[p]);
        int na = n0 + 2 * p, nb = na + 1;
        if (na < NN) { g_xl1[(long)na * 512 + j] = l0; g_xr1[(long)na * 512 + j] = r0; }
        if (nb < NN) { g_xl1[(long)nb * 512 + j] = l1; g_xr1[(long)nb * 512 + j] = r1; }
    }
}

// ---------------- layer1 fused attention+softmax+aggregate ----------------
// block = 128 threads = 4 warps; warp h = head h of node blockIdx.x.
// Edge metadata preloaded per 32-chunk; edge loop unrolled x2 for ILP.
__global__ void k_node1(const int* __restrict__ src, const float* __restrict__ ea,
                        const float* __restrict__ We, const float* __restrict__ att,
                        const float* __restrict__ b1) {
    int n = blockIdx.x;
    int warp = threadIdx.x >> 5, lane = threadIdx.x & 31;
    int col = warp * 128 + lane * 4;
    float we0[4], we1[4], at[4];
    #pragma unroll
    for (int i = 0; i < 4; i++) {
        we0[i] = We[col + i];
        we1[i] = We[512 + col + i];
        at[i]  = att[col + i];
    }
    float4 vr = *(const float4*)&g_xr1[(long)n * 512 + col];
    float den = 0.f;
    float ax = 0.f, ay = 0.f, az = 0.f, aw = 0.f;
    int beg = g_rowptr[n], end = g_rowptr[n + 1];
    for (int chunk = beg; chunk < end; chunk += 32) {
        int cnt = min(32, end - chunk);
        int   myS  = 0;
        float myA0 = 0.f, myA1 = 0.f;
        if (lane < cnt) {
            int e = g_eid[chunk + lane];
            myS  = src[e];
            myA0 = ea[2 * e];
            myA1 = ea[2 * e + 1];
        }
        int t = 0;
        for (; t + 2 <= cnt; t += 2) {
            int   s0  = __shfl_sync(0xffffffffu, myS,  t);
            int   s1  = __shfl_sync(0xffffffffu, myS,  t + 1);
            float e00 = __shfl_sync(0xffffffffu, myA0, t);
            float e01 = __shfl_sync(0xffffffffu, myA1, t);
            float e10 = __shfl_sync(0xffffffffu, myA0, t + 1);
            float e11 = __shfl_sync(0xffffffffu, myA1, t + 1);
            float4 vl0 = *(const float4*)&g_xl1[(long)s0 * 512 + col];
            float4 vl1 = *(const float4*)&g_xl1[(long)s1 * 512 + col];
            float p0 = lrelu(vl0.x + vr.x + fmaf(e00, we0[0], e01 * we1[0])) * at[0]
                     + lrelu(vl0.y + vr.y + fmaf(e00, we0[1], e01 * we1[1])) * at[1]
                     + lrelu(vl0.z + vr.z + fmaf(e00, we0[2], e01 * we1[2])) * at[2]
                     + lrelu(vl0.w + vr.w + fmaf(e00, we0[3], e01 * we1[3])) * at[3];
            float p1 = lrelu(vl1.x + vr.x + fmaf(e10, we0[0], e11 * we1[0])) * at[0]
                     + lrelu(vl1.y + vr.y + fmaf(e10, we0[1], e11 * we1[1])) * at[1]
                     + lrelu(vl1.z + vr.z + fmaf(e10, we0[2], e11 * we1[2])) * at[2]
                     + lrelu(vl1.w + vr.w + fmaf(e10, we0[3], e11 * we1[3])) * at[3];
            float w0 = warpsum_all(p0);
            float w1 = warpsum_all(p1);
            float pe0 = __expf(w0);
            float pe1 = __expf(w1);
            den += pe0 + pe1;
            ax = fmaf(pe0, vl0.x, fmaf(pe1, vl1.x, ax));
            ay = fmaf(pe0, vl0.y, fmaf(pe1, vl1.y, ay));
            az = fmaf(pe0, vl0.z, fmaf(pe1, vl1.z, az));
            aw = fmaf(pe0, vl0.w, fmaf(pe1, vl1.w, aw));
        }
        if (t < cnt) {
            int   s0  = __shfl_sync(0xffffffffu, myS,  t);
            float e00 = __shfl_sync(0xffffffffu, myA0, t);
            float e01 = __shfl_sync(0xffffffffu, myA1, t);
            float4 vl0 = *(const float4*)&g_xl1[(long)s0 * 512 + col];
            float p0 = lrelu(vl0.x + vr.x + fmaf(e00, we0[0], e01 * we1[0])) * at[0]
                     + lrelu(vl0.y + vr.y + fmaf(e00, we0[1], e01 * we1[1])) * at[1]
                     + lrelu(vl0.z + vr.z + fmaf(e00, we0[2], e01 * we1[2])) * at[2]
                     + lrelu(vl0.w + vr.w + fmaf(e00, we0[3], e01 * we1[3])) * at[3];
            float pe0 = __expf(warpsum_all(p0));
            den += pe0;
            ax = fmaf(pe0, vl0.x, ax);
            ay = fmaf(pe0, vl0.y, ay);
            az = fmaf(pe0, vl0.z, az);
            aw = fmaf(pe0, vl0.w, aw);
        }
    }
    {   // self loop
        float ea0 = g_loopea[2 * n], ea1 = g_loopea[2 * n + 1];
        float4 vl = *(const float4*)&g_xl1[(long)n * 512 + col];
        float p = lrelu(vl.x + vr.x + fmaf(ea0, we0[0], ea1 * we1[0])) * at[0]
                + lrelu(vl.y + vr.y + fmaf(ea0, we0[1], ea1 * we1[1])) * at[1]
                + lrelu(vl.z + vr.z + fmaf(ea0, we0[2], ea1 * we1[2])) * at[2]
                + lrelu(vl.w + vr.w + fmaf(ea0, we0[3], ea1 * we1[3])) * at[3];
        float pe = __expf(warpsum_all(p));
        den += pe;
        ax = fmaf(pe, vl.x, ax);
        ay = fmaf(pe, vl.y, ay);
        az = fmaf(pe, vl.z, az);
        aw = fmaf(pe, vl.w, aw);
    }
    float inv = 1.f / den;
    float4 o;
    o.x = elu1(fmaf(ax, inv, b1[col + 0]));
    o.y = elu1(fmaf(ay, inv, b1[col + 1]));
    o.z = elu1(fmaf(az, inv, b1[col + 2]));
    o.w = elu1(fmaf(aw, inv, b1[col + 3]));
    *(float4*)&g_h1[(long)n * 512 + col] = o;
}

// ---------------- layer2 projections: dual GEMM K=512, FFMA2 -------------
// 128 threads (thread j = output col), 16 nodes/block (R5 proven shape).
__global__ void __launch_bounds__(128) k_gemm2(
        const float* __restrict__ Wl, const float* __restrict__ Wr) {
    __shared__ __align__(16) float sh[512 * 18];
    int n0 = blockIdx.x * 16;
    int j = threadIdx.x;
    for (int t = j; t < 16 * 512; t += 128) {
        int n = t >> 9, k = t & 511;
        int node = n0 + n;
        sh[k * 18 + n] = (node < NN) ? g_h1[(long)node * 512 + k] : 0.f;
    }
    __syncthreads();
    unsigned long long accl[8], accr[8];
    #pragma unroll
    for (int p = 0; p < 8; p++) { accl[p] = 0ull; accr[p] = 0ull; }
    for (int k = 0; k < 512; k++) {
        unsigned long long wl2 = splat2(Wl[k * 128 + j]);
        unsigned long long wr2 = splat2(Wr[k * 128 + j]);
        const unsigned long long* row = (const unsigned long long*)&sh[k * 18];
        #pragma unroll
        for (int p = 0; p < 8; p++) {
            unsigned long long h2 = row[p];
            ffma2(accl[p], h2, wl2);
            ffma2(accr[p], h2, wr2);
        }
    }
    #pragma unroll
    for (int p = 0; p < 8; p++) {
        float l0, l1, r0, r1;
        unpack2(l0, l1, accl[p]);
        unpack2(r0, r1, accr[p]);
        int na = n0 + 2 * p, nb = na + 1;
        if (na < NN) { g_xl2[(long)na * 128 + j] = l0; g_xr2[(long)na * 128 + j] = r0; }
        if (nb < NN) { g_xl2[(long)nb * 128 + j] = l1; g_xr2[(long)nb * 128 + j] = r1; }
    }
}

// ---------------- layer2 fused attention+softmax+aggregate+FC -------------
// warp per node (1 head, 128 cols, 4 cols/lane); edge loop unrolled x2.
__global__ void k_node2(const int* __restrict__ src, const float* __restrict__ ea,
                        const float* __restrict__ We, const float* __restrict__ att,
                        const float* __restrict__ b2, const float* __restrict__ Wfc,
                        const float* __restrict__ bfc, float* __restrict__ out) {
    int warp = threadIdx.x >> 5, lane = threadIdx.x & 31;
    int n = blockIdx.x * 8 + warp;
    if (n >= NN) return;
    int col = lane * 4;
    float we0[4], we1[4], at[4];
    #pragma unroll
    for (int i = 0; i < 4; i++) {
        we0[i] = We[col + i];
        we1[i] = We[128 + col + i];
        at[i]  = att[col + i];
    }
    float4 vr = *(const float4*)&g_xr2[(long)n * 128 + col];
    float den = 0.f;
    float ax = 0.f, ay = 0.f, az = 0.f, aw = 0.f;
    int beg = g_rowptr[n], end = g_rowptr[n + 1];
    for (int chunk = beg; chunk < end; chunk += 32) {
        int cnt = min(32, end - chunk);
        int   myS  = 0;
        float myA0 = 0.f, myA1 = 0.f;
        if (lane < cnt) {
            int e = g_eid[chunk + lane];
            myS  = src[e];
            myA0 = ea[2 * e];
            myA1 = ea[2 * e + 1];
        }
        int t = 0;
        for (; t + 2 <= cnt; t += 2) {
            int   s0  = __shfl_sync(0xffffffffu, myS,  t);
            int   s1  = __shfl_sync(0xffffffffu, myS,  t + 1);
            float e00 = __shfl_sync(0xffffffffu, myA0, t);
            float e01 = __shfl_sync(0xffffffffu, myA1, t);
            float e10 = __shfl_sync(0xffffffffu, myA0, t + 1);
            float e11 = __shfl_sync(0xffffffffu, myA1, t + 1);
            float4 vl0 = *(const float4*)&g_xl2[(long)s0 * 128 + col];
            float4 vl1 = *(const float4*)&g_xl2[(long)s1 * 128 + col];
            float p0 = lrelu(vl0.x + vr.x + fmaf(e00, we0[0], e01 * we1[0])) * at[0]
                     + lrelu(vl0.y + vr.y + fmaf(e00, we0[1], e01 * we1[1])) * at[1]
                     + lrelu(vl0.z + vr.z + fmaf(e00, we0[2], e01 * we1[2])) * at[2]
                     + lrelu(vl0.w + vr.w + fmaf(e00, we0[3], e01 * we1[3])) * at[3];
            float p1 = lrelu(vl1.x + vr.x + fmaf(e10, we0[0], e11 * we1[0])) * at[0]
                     + lrelu(vl1.y + vr.y + fmaf(e10, we0[1], e11 * we1[1])) * at[1]
                     + lrelu(vl1.z + vr.z + fmaf(e10, we0[2], e11 * we1[2])) * at[2]
                     + lrelu(vl1.w + vr.w + fmaf(e10, we0[3], e11 * we1[3])) * at[3];
            float w0 = warpsum_all(p0);
            float w1 = warpsum_all(p1);
            float pe0 = __expf(w0);
            float pe1 = __expf(w1);
            den += pe0 + pe1;
            ax = fmaf(pe0, vl0.x, fmaf(pe1, vl1.x, ax));
            ay = fmaf(pe0, vl0.y, fmaf(pe1, vl1.y, ay));
            az = fmaf(pe0, vl0.z, fmaf(pe1, vl1.z, az));
            aw = fmaf(pe0, vl0.w, fmaf(pe1, vl1.w, aw));
        }
        if (t < cnt) {
            int   s0  = __shfl_sync(0xffffffffu, myS,  t);
            float e00 = __shfl_sync(0xffffffffu, myA0, t);
            float e01 = __shfl_sync(0xffffffffu, myA1, t);
            float4 vl0 = *(const float4*)&g_xl2[(long)s0 * 128 + col];
            float p0 = lrelu(vl0.x + vr.x + fmaf(e00, we0[0], e01 * we1[0])) * at[0]
                     + lrelu(vl0.y + vr.y + fmaf(e00, we0[1], e01 * we1[1])) * at[1]
                     + lrelu(vl0.z + vr.z + fmaf(e00, we0[2], e01 * we1[2])) * at[2]
                     + lrelu(vl0.w + vr.w + fmaf(e00, we0[3], e01 * we1[3])) * at[3];
            float pe0 = __expf(warpsum_all(p0));
            den += pe0;
            ax = fmaf(pe0, vl0.x, ax);
            ay = fmaf(pe0, vl0.y, ay);
            az = fmaf(pe0, vl0.z, az);
            aw = fmaf(pe0, vl0.w, aw);
        }
    }
    {   // self loop
        float ea0 = g_loopea[2 * n], ea1 = g_loopea[2 * n + 1];
        float4 vl = *(const float4*)&g_xl2[(long)n * 128 + col];
        float p = lrelu(vl.x + vr.x + fmaf(ea0, we0[0], ea1 * we1[0])) * at[0]
                + lrelu(vl.y + vr.y + fmaf(ea0, we0[1], ea1 * we1[1])) * at[1]
                + lrelu(vl.z + vr.z + fmaf(ea0, we0[2], ea1 * we1[2])) * at[2]
                + lrelu(vl.w + vr.w + fmaf(ea0, we0[3], ea1 * we1[3])) * at[3];
        float pe = __expf(warpsum_all(p));
        den += pe;
        ax = fmaf(pe, vl.x, ax);
        ay = fmaf(pe, vl.y, ay);
        az = fmaf(pe, vl.z, az);
        aw = fmaf(pe, vl.w, aw);
    }
    float inv = 1.f / den;
    float h0 = elu1(fmaf(ax, inv, b2[col + 0]));
    float h1 = elu1(fmaf(ay, inv, b2[col + 1]));
    float h2 = elu1(fmaf(az, inv, b2[col + 2]));
    float h3 = elu1(fmaf(aw, inv, b2[col + 3]));
    float a0 = h0 * Wfc[(col + 0) * 2] + h1 * Wfc[(col + 1) * 2]
             + h2 * Wfc[(col + 2) * 2] + h3 * Wfc[(col + 3) * 2];
    float a1 = h0 * Wfc[(col + 0) * 2 + 1] + h1 * Wfc[(col + 1) * 2 + 1]
             + h2 * Wfc[(col + 2) * 2 + 1] + h3 * Wfc[(col + 3) * 2 + 1];
    a0 = warpsum(a0);
    a1 = warpsum(a1);
    if (lane == 0) {
        out[n * 2]     = a0 + bfc[0];
        out[n * 2 + 1] = a1 + bfc[1];
    }
}

// ---------------- launcher ----------------------------------------------
extern "C" void kernel_launch(void* const* d_in, const int* in_sizes, int n_in,
                              void* d_out, int out_size) {
    const float* x     = (const float*)d_in[0];
    const int*   ei    = (const int*)  d_in[1];
    const float* ea    = (const float*)d_in[2];
    const int*   rtype = (const int*)  d_in[3];
    const float* aaemb = (const float*)d_in[4];
    const float* W1l   = (const float*)d_in[5];
    const float* W1r   = (const float*)d_in[6];
    const float* W1e   = (const float*)d_in[7];
    const float* att1  = (const float*)d_in[8];
    const float* b1    = (const float*)d_in[9];
    const float* W2l   = (const float*)d_in[10];
    const float* W2r   = (const float*)d_in[11];
    const float* W2e   = (const float*)d_in[12];
    const float* att2  = (const float*)d_in[13];
    const float* b2    = (const float*)d_in[14];
    const float* Wfc   = (const float*)d_in[15];
    const float* bfc   = (const float*)d_in[16];
    float* out = (float*)d_out;

    const int* src = ei;
    const int* dst = ei + EE;

    k_init<<<(NN + 255) / 256, 256>>>();
    k_pre<<<(EE + 255) / 256, 256>>>(dst, ea);
    k_scan<<<1, 1024>>>();
    k_place<<<(EE + 255) / 256, 256>>>(dst);
    k_loopea_norm<<<(NN + 255) / 256, 256>>>();
    k_gemm1<<<(NN + 15) / 16, 512>>>(x, rtype, aaemb, W1l, W1r);
    k_node1<<<NN, 128>>>(src, ea, W1e, att1, b1);
    k_gemm2<<<(NN + 15) / 16, 128>>>(W2l, W2r);
    k_node2<<<(NN + 7) / 8, 256>>>(src, ea, W2e, att2, b2, Wfc, bfc, out);
}